// round 5
// baseline (speedup 1.0000x reference)
#include <cuda_runtime.h>

// Quan2d, round 5: cooperative smem staging (1 LDG.128/thread), padded tile
// (no per-read predication), scalar tangent-form gates, fused square+reduce.
//
// RY(th) = cos(th/2)*[[1,-t],[t,1]]; uniform scalars cancel in
// <Z_w> = 2*S_w/n - 1,  S_w = sum_{bit_w=0} u_s^2,  n = sum u_s^2.
// CNOT ring permutation h: {0,13,3,14,6,11,5,8,12,1,15,2,10,7,9,4}.

__host__ __device__ constexpr int permIdx(int s) {
    int b0 = (s >> 3) & 1, b1 = (s >> 2) & 1, b2 = (s >> 1) & 1, b3 = s & 1;
    int h0 = b0 ^ b3, h1 = b0 ^ b1 ^ b3, h2 = b1 ^ b2, h3 = b2 ^ b3;
    return (h0 << 3) | (h1 << 2) | (h2 << 1) | h3;
}

#define SROW 36   // smem row stride in floats (34 used + 2 slack; 144B = 16B-aligned)

__global__ __launch_bounds__(256)
void quan2d_kernel(const float* __restrict__ x,
                   const float* __restrict__ w8,
                   float* __restrict__ out)
{
    __shared__ float tile[34 * SROW];   // rows 0..33, cols 0..35 (pad zeroed)
    __shared__ float ct[8];

    const int tid = threadIdx.x;

    // tangents (warp 0 lanes 0..7)
    if (tid < 8) {
        float sv, cv;
        sincosf(0.5f * w8[tid], &sv, &cv);
        ct[tid] = sv / cv;
    }

    // zero the pad: cols 32..35 of rows 0..31, and rows 32..33 (all 36 cols)
    if (tid < 128) {
        tile[(tid >> 2) * SROW + 32 + (tid & 3)] = 0.f;
    } else if (tid < 200) {
        const int j = tid - 128;            // 0..71
        const int r = (j >= 36) ? 33 : 32;
        const int c = (j >= 36) ? (j - 36) : j;
        tile[r * SROW + c] = 0.f;
    }

    // stage image: thread tid loads floats [4*tid, 4*tid+4) of the 32x32 image
    const int b = blockIdx.x;
    {
        const float4 v = __ldg((const float4*)(x + (size_t)b * 1024) + tid);
        const int r = tid >> 3;             // image row 0..31
        const int c = (tid & 7) * 4;        // image col 0,4,..,28
        *(float4*)&tile[r * SROW + c] = v;
    }
    __syncthreads();

    // --- read 4x4 patch from smem (no predication; pad is zero) ---
    const int pr = tid >> 4;   // patch row 0..15
    const int pc = tid & 15;   // patch col 0..15
    float a[16];
    #pragma unroll
    for (int i = 0; i < 4; i++) {
        const float* rp = &tile[(2 * pr + i) * SROW + 2 * pc];
        const float2 A = *(const float2*)rp;
        const float2 B = *(const float2*)(rp + 2);
        a[4 * i + 0] = A.x;
        a[4 * i + 1] = A.y;
        a[4 * i + 2] = B.x;
        a[4 * i + 3] = B.y;
    }

    // --- RY layer 1 (tangent form): gate g acts on bit (8 >> g) ---
    #pragma unroll
    for (int g = 0; g < 4; g++) {
        const float tg = ct[g];
        const int BIT = 8 >> g;
        #pragma unroll
        for (int lo = 0; lo < 16; lo++) {
            if (lo & BIT) continue;
            const float xx = a[lo], yy = a[lo | BIT];
            a[lo]       = fmaf(-tg, yy, xx);
            a[lo | BIT] = fmaf( tg, xx, yy);
        }
    }

    // --- CNOT ring: compile-time register permutation ---
    float t[16];
    #pragma unroll
    for (int s = 0; s < 16; s++) t[s] = a[permIdx(s)];

    // --- RY layer 2 (tangent form) ---
    #pragma unroll
    for (int g = 0; g < 4; g++) {
        const float tg = ct[4 + g];
        const int BIT = 8 >> g;
        #pragma unroll
        for (int lo = 0; lo < 16; lo++) {
            if (lo & BIT) continue;
            const float xx = t[lo], yy = t[lo | BIT];
            t[lo]       = fmaf(-tg, yy, xx);
            t[lo | BIT] = fmaf( tg, xx, yy);
        }
    }

    // --- fused squares + reduction ---
    // qe[k] = t[2k]^2 ; s1[k] = t[2k+1]^2 + qe[k]
    float qe[8], s1[8];
    #pragma unroll
    for (int k = 0; k < 8; k++) {
        qe[k] = t[2 * k] * t[2 * k];
        s1[k] = fmaf(t[2 * k + 1], t[2 * k + 1], qe[k]);
    }
    float s2[4];
    #pragma unroll
    for (int k = 0; k < 4; k++) s2[k] = s1[2 * k] + s1[2 * k + 1];
    const float s3a = s2[0] + s2[1];
    const float s3b = s2[2] + s2[3];
    const float n   = s3a + s3b;

    const float S0 = s3a;                                   // wire0: bit3==0
    const float S1 = s2[0] + s2[2];                         // wire1: bit2==0
    const float S2 = (s1[0] + s1[2]) + (s1[4] + s1[6]);     // wire2: bit1==0
    const float S3 = ((qe[0] + qe[1]) + (qe[2] + qe[3]))    // wire3: bit0==0
                   + ((qe[4] + qe[5]) + (qe[6] + qe[7]));

    // --- epilogue: <Z_w> = 2*S_w/n - 1 ---
    const float r2 = 2.0f * __frcp_rn(n);
    float4 o;
    o.x = fmaf(S0, r2, -1.0f);
    o.y = fmaf(S1, r2, -1.0f);
    o.z = fmaf(S2, r2, -1.0f);
    o.w = fmaf(S3, r2, -1.0f);
    ((float4*)out)[(size_t)b * 256 + tid] = o;
}

extern "C" void kernel_launch(void* const* d_in, const int* in_sizes, int n_in,
                              void* d_out, int out_size)
{
    const float* x = (const float*)d_in[0];   // [B,1,32,32] fp32
    const float* w = (const float*)d_in[1];   // [1,8] fp32
    const int B = in_sizes[0] / 1024;
    quan2d_kernel<<<B, 256>>>(x, w, (float*)d_out);
}

// round 6
// speedup vs baseline: 1.0498x; 1.0498x over previous
#include <cuda_runtime.h>

// Quan2d, round 6: R4 skeleton (direct LDG, scalar tangent gates, fused
// square+tree reduce) minus all per-CTA setup overhead:
//  - tangents precomputed by a tiny pre-kernel into a __device__ global
//    (main kernel: 2x LDG.128, no shared, no syncthreads, no sincos)
//  - minimal border predication (rows 2pr,2pr+1 provably in-bounds)
//  - rcp.approx for the normalization
//
// Math: RY(th) = cos(th/2)*[[1,-t],[t,1]], t = tan(th/2); uniform scalars
// cancel in <Z_w> = 2*S_w/n - 1, S_w = sum_{bit_w=0} u^2, n = sum u^2.
// CNOT ring perm h: {0,13,3,14,6,11,5,8,12,1,15,2,10,7,9,4}.

__host__ __device__ constexpr int permIdx(int s) {
    int b0 = (s >> 3) & 1, b1 = (s >> 2) & 1, b2 = (s >> 1) & 1, b3 = s & 1;
    int h0 = b0 ^ b3, h1 = b0 ^ b1 ^ b3, h2 = b1 ^ b2, h3 = b2 ^ b3;
    return (h0 << 3) | (h1 << 2) | (h2 << 1) | h3;
}

__device__ float g_tang[8];

__global__ void tang_kernel(const float* __restrict__ w8) {
    if (threadIdx.x < 8) {
        float sv, cv;
        sincosf(0.5f * w8[threadIdx.x], &sv, &cv);
        g_tang[threadIdx.x] = sv / cv;
    }
}

__device__ __forceinline__ float frcp_approx(float v) {
    float r; asm("rcp.approx.f32 %0, %1;" : "=f"(r) : "f"(v)); return r;
}

__global__ __launch_bounds__(256)
void quan2d_kernel(const float* __restrict__ x,
                   float* __restrict__ out)
{
    const int tid = threadIdx.x;
    const int b   = blockIdx.x;
    const int pr  = tid >> 4;   // patch row 0..15
    const int pc  = tid & 15;   // patch col 0..15
    const float* img = x + (size_t)b * 1024;

    // --- load 4x4 patch, zero-padded bottom/right ---
    // rows 2pr, 2pr+1 are always < 32; rows 2pr+2, 2pr+3 need pr < 15.
    const bool pA = (pr < 15);
    const bool pB = (pc < 15);
    const float2 z2 = make_float2(0.f, 0.f);

    float a[16];
    #pragma unroll
    for (int i = 0; i < 4; i++) {
        const float2* rowp = (const float2*)(img + (2 * pr + i) * 32 + 2 * pc);
        const bool rok = (i < 2) || pA;
        float2 A = rok ? __ldg(rowp) : z2;
        float2 B = (rok && pB) ? __ldg(rowp + 1) : z2;
        a[4 * i + 0] = A.x;
        a[4 * i + 1] = A.y;
        a[4 * i + 2] = B.x;
        a[4 * i + 3] = B.y;
    }

    // --- tangents (L1-resident global, no shared / no sync) ---
    const float4 t03 = __ldg((const float4*)g_tang);
    const float4 t47 = __ldg((const float4*)g_tang + 1);
    const float ct[8] = { t03.x, t03.y, t03.z, t03.w,
                          t47.x, t47.y, t47.z, t47.w };

    // --- RY layer 1 (tangent form): gate g acts on bit (8 >> g) ---
    #pragma unroll
    for (int g = 0; g < 4; g++) {
        const float tg = ct[g];
        const int BIT = 8 >> g;
        #pragma unroll
        for (int lo = 0; lo < 16; lo++) {
            if (lo & BIT) continue;
            const float xx = a[lo], yy = a[lo | BIT];
            a[lo]       = fmaf(-tg, yy, xx);
            a[lo | BIT] = fmaf( tg, xx, yy);
        }
    }

    // --- CNOT ring: compile-time register permutation ---
    float t[16];
    #pragma unroll
    for (int s = 0; s < 16; s++) t[s] = a[permIdx(s)];

    // --- RY layer 2 (tangent form) ---
    #pragma unroll
    for (int g = 0; g < 4; g++) {
        const float tg = ct[4 + g];
        const int BIT = 8 >> g;
        #pragma unroll
        for (int lo = 0; lo < 16; lo++) {
            if (lo & BIT) continue;
            const float xx = t[lo], yy = t[lo | BIT];
            t[lo]       = fmaf(-tg, yy, xx);
            t[lo | BIT] = fmaf( tg, xx, yy);
        }
    }

    // --- fused squares + tree reduction ---
    float qe[8], s1[8];
    #pragma unroll
    for (int k = 0; k < 8; k++) {
        qe[k] = t[2 * k] * t[2 * k];
        s1[k] = fmaf(t[2 * k + 1], t[2 * k + 1], qe[k]);
    }
    float s2[4];
    #pragma unroll
    for (int k = 0; k < 4; k++) s2[k] = s1[2 * k] + s1[2 * k + 1];
    const float s3a = s2[0] + s2[1];
    const float s3b = s2[2] + s2[3];
    const float n   = s3a + s3b;

    const float S0 = s3a;                                   // wire0: bit3==0
    const float S1 = s2[0] + s2[2];                         // wire1: bit2==0
    const float S2 = (s1[0] + s1[2]) + (s1[4] + s1[6]);     // wire2: bit1==0
    const float S3 = ((qe[0] + qe[1]) + (qe[2] + qe[3]))    // wire3: bit0==0
                   + ((qe[4] + qe[5]) + (qe[6] + qe[7]));

    // --- epilogue: <Z_w> = 2*S_w/n - 1 ---
    const float r2 = 2.0f * frcp_approx(n);
    float4 o;
    o.x = fmaf(S0, r2, -1.0f);
    o.y = fmaf(S1, r2, -1.0f);
    o.z = fmaf(S2, r2, -1.0f);
    o.w = fmaf(S3, r2, -1.0f);
    ((float4*)out)[(size_t)b * 256 + tid] = o;
}

extern "C" void kernel_launch(void* const* d_in, const int* in_sizes, int n_in,
                              void* d_out, int out_size)
{
    const float* x = (const float*)d_in[0];   // [B,1,32,32] fp32
    const float* w = (const float*)d_in[1];   // [1,8] fp32
    const int B = in_sizes[0] / 1024;
    tang_kernel<<<1, 32>>>(w);
    quan2d_kernel<<<B, 256>>>(x, (float*)d_out);
}

// round 7
// speedup vs baseline: 1.1777x; 1.1218x over previous
#include <cuda_runtime.h>

// Quan2d, round 7: two horizontally adjacent patches per thread (scalar),
// amortizing loads (float4+float2 per row covers both patches), addressing,
// tangent broadcast, and stores. In-block tangent setup via MUFU __tanf
// (no pre-kernel launch node).
//
// Math: RY(th) = cos(th/2)*[[1,-t],[t,1]], t = tan(th/2); uniform scalars
// cancel in <Z_w> = 2*S_w/n - 1, S_w = sum_{bit_w=0} u^2, n = sum u^2.
// CNOT ring perm h: {0,13,3,14,6,11,5,8,12,1,15,2,10,7,9,4}.

__host__ __device__ constexpr int permIdx(int s) {
    int b0 = (s >> 3) & 1, b1 = (s >> 2) & 1, b2 = (s >> 1) & 1, b3 = s & 1;
    int h0 = b0 ^ b3, h1 = b0 ^ b1 ^ b3, h2 = b1 ^ b2, h3 = b2 ^ b3;
    return (h0 << 3) | (h1 << 2) | (h2 << 1) | h3;
}

__device__ __forceinline__ float frcp_approx(float v) {
    float r; asm("rcp.approx.f32 %0, %1;" : "=f"(r) : "f"(v)); return r;
}

// Full circuit + reduction on one 16-amplitude patch; returns <Z_0..3>.
__device__ __forceinline__ float4 run_patch(float (&a)[16], const float* ct) {
    // RY layer 1
    #pragma unroll
    for (int g = 0; g < 4; g++) {
        const float tg = ct[g];
        const int BIT = 8 >> g;
        #pragma unroll
        for (int lo = 0; lo < 16; lo++) {
            if (lo & BIT) continue;
            const float xx = a[lo], yy = a[lo | BIT];
            a[lo]       = fmaf(-tg, yy, xx);
            a[lo | BIT] = fmaf( tg, xx, yy);
        }
    }
    // CNOT ring permutation
    float t[16];
    #pragma unroll
    for (int s = 0; s < 16; s++) t[s] = a[permIdx(s)];
    // RY layer 2
    #pragma unroll
    for (int g = 0; g < 4; g++) {
        const float tg = ct[4 + g];
        const int BIT = 8 >> g;
        #pragma unroll
        for (int lo = 0; lo < 16; lo++) {
            if (lo & BIT) continue;
            const float xx = t[lo], yy = t[lo | BIT];
            t[lo]       = fmaf(-tg, yy, xx);
            t[lo | BIT] = fmaf( tg, xx, yy);
        }
    }
    // fused squares + tree reduction
    float qe[8], s1[8];
    #pragma unroll
    for (int k = 0; k < 8; k++) {
        qe[k] = t[2 * k] * t[2 * k];
        s1[k] = fmaf(t[2 * k + 1], t[2 * k + 1], qe[k]);
    }
    float s2[4];
    #pragma unroll
    for (int k = 0; k < 4; k++) s2[k] = s1[2 * k] + s1[2 * k + 1];
    const float s3a = s2[0] + s2[1];
    const float s3b = s2[2] + s2[3];
    const float n   = s3a + s3b;

    const float S0 = s3a;
    const float S1 = s2[0] + s2[2];
    const float S2 = (s1[0] + s1[2]) + (s1[4] + s1[6]);
    const float S3 = ((qe[0] + qe[1]) + (qe[2] + qe[3]))
                   + ((qe[4] + qe[5]) + (qe[6] + qe[7]));

    const float r2 = 2.0f * frcp_approx(n);
    return make_float4(fmaf(S0, r2, -1.0f), fmaf(S1, r2, -1.0f),
                       fmaf(S2, r2, -1.0f), fmaf(S3, r2, -1.0f));
}

__global__ __launch_bounds__(256)
void quan2d_kernel(const float* __restrict__ x,
                   const float* __restrict__ w8,
                   float* __restrict__ out)
{
    __shared__ float cts[8];
    const int tid = threadIdx.x;
    if (tid < 8) cts[tid] = __tanf(0.5f * w8[tid]);
    __syncthreads();

    float ct[8];
    #pragma unroll
    for (int i = 0; i < 8; i++) ct[i] = cts[i];

    const int b  = blockIdx.x * 2 + (tid >> 7);   // image
    const int t7 = tid & 127;
    const int pr = t7 >> 3;                        // patch row 0..15
    const int k  = t7 & 7;                         // pair idx; patches pc=2k,2k+1
    const float* img = x + (size_t)b * 1024;

    // --- load rows 2pr..2pr+3, cols 4k..4k+5 (zero-pad bottom/right) ---
    // rows 2pr,2pr+1 always < 32; rows 2pr+2,2pr+3 need pr<15; G needs k<7.
    const bool pA = (pr < 15);
    const bool pB = (k < 7);
    float a0[16], a1[16];
    #pragma unroll
    for (int i = 0; i < 4; i++) {
        const float* base = img + (2 * pr + i) * 32 + 4 * k;
        const bool rok = (i < 2) || pA;
        float4 F = rok ? __ldg((const float4*)base)
                       : make_float4(0.f, 0.f, 0.f, 0.f);
        float2 G = (rok && pB) ? __ldg((const float2*)(base + 4))
                               : make_float2(0.f, 0.f);
        a0[4 * i + 0] = F.x; a0[4 * i + 1] = F.y;
        a0[4 * i + 2] = F.z; a0[4 * i + 3] = F.w;
        a1[4 * i + 0] = F.z; a1[4 * i + 1] = F.w;
        a1[4 * i + 2] = G.x; a1[4 * i + 3] = G.y;
    }

    const float4 o0 = run_patch(a0, ct);
    const float4 o1 = run_patch(a1, ct);

    float4* op = (float4*)out + (size_t)b * 256 + pr * 16 + 2 * k;
    op[0] = o0;
    op[1] = o1;
}

extern "C" void kernel_launch(void* const* d_in, const int* in_sizes, int n_in,
                              void* d_out, int out_size)
{
    const float* x = (const float*)d_in[0];   // [B,1,32,32] fp32
    const float* w = (const float*)d_in[1];   // [1,8] fp32
    const int B = in_sizes[0] / 1024;
    quan2d_kernel<<<B / 2, 256>>>(x, w, (float*)d_out);
}